// round 15
// baseline (speedup 1.0000x reference)
#include <cuda_runtime.h>
#include <cuda_fp16.h>
#include <math_constants.h>
#include <cstdint>

// Problem constants
#define B   4
#define S   2048
#define NX  1024
#define H   16
#define D   64
#define M_TOT (B * S)   // 8192

// ---------------------------------------------------------------------------
// Global scratch (uint32 units; halves inside)
// GEMM tiles: [blk128][kblk32][128 rows][24 words] (word-pair permuted)
// Flash tiles: [bh][kt][64 rows][40 words] (word-pair permuted, 32 data words)
// ---------------------------------------------------------------------------
__device__ float    g_qkv[(size_t)M_TOT * 3 * NX];          // fp32 QKV
__device__ uint32_t g_xh [(size_t)64 * 32 * 128 * 24];      // x fp16 tiles
__device__ uint32_t g_w1h[(size_t)24 * 32 * 128 * 24];      // attn_w^T fp16 tiles
__device__ uint32_t g_w2h[(size_t)8  * 32 * 128 * 24];      // proj_w^T fp16 tiles
__device__ uint32_t g_cxh[(size_t)64 * 32 * 128 * 24];      // ctx fp16 tiles
__device__ uint32_t g_kh [(size_t)64 * 32 * 64 * 40];       // K fp16 tiles [key][d]
__device__ uint32_t g_vh [(size_t)64 * 32 * 64 * 40];       // V^T fp16 tiles [d][key]

// ---------------------------------------------------------------------------
// Helpers
// ---------------------------------------------------------------------------
__device__ __forceinline__ uint32_t pack2(float lo, float hi) {
    __half2 h = __floats2half2_rn(lo, hi);
    return *(uint32_t*)&h;
}

// word-pair permutation within EACH 8-word group: (tig, tig+4) -> (2tig, 2tig+1)
// Preserves all bits >= 3 (groups). FIX vs round 14: (w & ~7), not (w & 8).
__device__ __forceinline__ int permw(int w) {
    return (w & ~7) | ((w & 3) << 1) | ((w >> 2) & 1);
}

// mma.sync m16n8k16 f16: D = A*B + D (fp32 accum)
__device__ __forceinline__ void mma16(float* c, const uint32_t* a,
                                      uint32_t b0, uint32_t b1) {
    asm volatile(
        "mma.sync.aligned.m16n8k16.row.col.f32.f16.f16.f32 "
        "{%0,%1,%2,%3}, {%4,%5,%6,%7}, {%8,%9}, {%0,%1,%2,%3};"
        : "+f"(c[0]), "+f"(c[1]), "+f"(c[2]), "+f"(c[3])
        : "r"(a[0]), "r"(a[1]), "r"(a[2]), "r"(a[3]), "r"(b0), "r"(b1));
}

// ---------------------------------------------------------------------------
// prep_x: x fp32 -> fp16 permuted tiles. grid (K/32, M/128), 256 thr.
// ---------------------------------------------------------------------------
__global__ __launch_bounds__(256)
void prep_x(const float* __restrict__ x, uint32_t* __restrict__ xh,
            int K, int KB)
{
    const int kblk = blockIdx.x, mblk = blockIdx.y;
    const int tid = threadIdx.x;
    const size_t tile = ((size_t)mblk * KB + kblk) * 128 * 24;
    for (int idx = tid; idx < 128 * 8; idx += 256) {
        const int r = idx >> 3, ve = idx & 7;
        float4 v = *(const float4*)(x + (size_t)(mblk * 128 + r) * K + kblk * 32 + ve * 4);
        xh[tile + r * 24 + permw(2 * ve)]     = pack2(v.x, v.y);
        xh[tile + r * 24 + permw(2 * ve + 1)] = pack2(v.z, v.w);
    }
}

// ---------------------------------------------------------------------------
// transpose_h: W[k][n] fp32 -> Wt fp16 permuted tiles. grid (N/32, K/32).
// ---------------------------------------------------------------------------
__global__ void transpose_h(const float* __restrict__ W, uint32_t* __restrict__ Wt,
                            int K, int N, int KB)
{
    __shared__ float t[32][33];
    const int k0 = blockIdx.y * 32, n0 = blockIdx.x * 32;
    const int x = threadIdx.x, y = threadIdx.y;
#pragma unroll
    for (int i = 0; i < 32; i += 8)
        t[y + i][x] = W[(size_t)(k0 + y + i) * N + n0 + x];
    __syncthreads();
    __half* out = (__half*)Wt;
#pragma unroll
    for (int i = 0; i < 32; i += 8) {
        const int n = n0 + y + i, k = k0 + x;
        const int kw = (k & 31) >> 1;
        const size_t idx = (((size_t)(n >> 7) * KB + (k >> 5)) * 128 + (n & 127)) * 48
                           + 2 * permw(kw) + (k & 1);
        out[idx] = __float2half_rn(t[x][y + i]);
    }
}

// ---------------------------------------------------------------------------
// prep_kv: qkv fp32 -> K tiles [key][d] and V^T tiles [d][key], permuted.
// grid (S/64, B*H), 256 thr. Rows have 32 data words (64 halves).
// ---------------------------------------------------------------------------
__global__ __launch_bounds__(256)
void prep_kv(const float* __restrict__ qkv, uint32_t* __restrict__ kh,
             uint32_t* __restrict__ vh)
{
    __shared__ float vs[64][65];
    const int bh = blockIdx.y;
    const int b = bh >> 4, h = bh & 15;
    const int kt = blockIdx.x;
    const int s0 = kt * 64;
    const int tid = threadIdx.x;

    const float* kbase = qkv + (size_t)b * S * (3 * NX) + NX + h * D;
    const float* vbase = qkv + (size_t)b * S * (3 * NX) + 2 * NX + h * D;
    const size_t tile = ((size_t)bh * 32 + kt) * 64 * 40;

    for (int idx = tid; idx < 64 * 16; idx += 256) {
        const int r  = idx >> 4;
        const int ve = idx & 15;
        const size_t grow = (size_t)(s0 + r) * (3 * NX) + ve * 4;
        float4 kv = *(const float4*)(kbase + grow);
        kh[tile + r * 40 + permw(2 * ve)]     = pack2(kv.x, kv.y);
        kh[tile + r * 40 + permw(2 * ve + 1)] = pack2(kv.z, kv.w);
        float4 vv = *(const float4*)(vbase + grow);
        vs[4 * ve + 0][r] = vv.x;
        vs[4 * ve + 1][r] = vv.y;
        vs[4 * ve + 2][r] = vv.z;
        vs[4 * ve + 3][r] = vv.w;
    }
    __syncthreads();

    for (int idx = tid; idx < 64 * 16; idx += 256) {
        const int d  = idx >> 4;
        const int ve = idx & 15;
        vh[tile + d * 40 + permw(2 * ve)]     = pack2(vs[d][4 * ve + 0], vs[d][4 * ve + 1]);
        vh[tile + d * 40 + permw(2 * ve + 1)] = pack2(vs[d][4 * ve + 2], vs[d][4 * ve + 3]);
    }
}

// ---------------------------------------------------------------------------
// fp16 mma GEMM on permuted tiles: C[M,N] = A @ Bt^T + bias
// Block 128x128, K-tile 64 (2 k-blocks/round), 256 threads, warp tile 64x32.
// All fragment loads are LDS.64 (conflict-free at stride 24).
// ---------------------------------------------------------------------------
__global__ __launch_bounds__(256)
void gemm_h(const uint32_t* __restrict__ At, const uint32_t* __restrict__ Bt,
            const float* __restrict__ bias, float* __restrict__ C,
            int N, int KB)
{
    extern __shared__ uint32_t gsw[];
    uint32_t* Asw = gsw;           // 2 k-blocks x 3072 words
    uint32_t* Bsw = gsw + 6144;

    const int tid  = threadIdx.x;
    const int wid  = tid >> 5;
    const int lane = tid & 31;
    const int g    = lane >> 2;
    const int tig  = lane & 3;

    const int nblk = blockIdx.x, mblk = blockIdx.y;
    const int wm = (wid >> 2) * 64;
    const int wn = (wid & 3) * 32;

    float c[4][4][4];
#pragma unroll
    for (int mi = 0; mi < 4; mi++)
#pragma unroll
        for (int ni = 0; ni < 4; ni++)
#pragma unroll
            for (int j = 0; j < 4; j++) c[mi][ni][j] = 0.f;

    const int KB2 = KB >> 1;
    for (int kc = 0; kc < KB2; kc++) {
        __syncthreads();
        const uint4* asrc = (const uint4*)(At + ((size_t)mblk * KB + 2 * kc) * 3072);
        const uint4* bsrc = (const uint4*)(Bt + ((size_t)nblk * KB + 2 * kc) * 3072);
        for (int i = tid; i < 3072; i += 256) {
            if (i < 1536) ((uint4*)Asw)[i] = asrc[i];
            else          ((uint4*)Bsw)[i - 1536] = bsrc[i - 1536];
        }
        __syncthreads();

#pragma unroll
        for (int kb = 0; kb < 2; kb++) {
            const uint32_t* Ab = Asw + kb * 3072;
            const uint32_t* Bb = Bsw + kb * 3072;
#pragma unroll
            for (int s = 0; s < 2; s++) {
                const int base = s * 8 + 2 * tig;
                uint32_t af[4][4], bf[4][2];
#pragma unroll
                for (int mi = 0; mi < 4; mi++) {
                    const int r = wm + mi * 16;
                    float2 lo = *(const float2*)&Ab[(r + g) * 24 + base];
                    float2 hi = *(const float2*)&Ab[(r + g + 8) * 24 + base];
                    af[mi][0] = __float_as_uint(lo.x);
                    af[mi][1] = __float_as_uint(hi.x);
                    af[mi][2] = __float_as_uint(lo.y);
                    af[mi][3] = __float_as_uint(hi.y);
                }
#pragma unroll
                for (int ni = 0; ni < 4; ni++) {
                    float2 bb = *(const float2*)&Bb[(wn + ni * 8 + g) * 24 + base];
                    bf[ni][0] = __float_as_uint(bb.x);
                    bf[ni][1] = __float_as_uint(bb.y);
                }
#pragma unroll
                for (int mi = 0; mi < 4; mi++)
#pragma unroll
                    for (int ni = 0; ni < 4; ni++)
                        mma16(c[mi][ni], af[mi], bf[ni][0], bf[ni][1]);
            }
        }
    }

#pragma unroll
    for (int mi = 0; mi < 4; mi++) {
        const int row0 = mblk * 128 + wm + mi * 16 + g;
#pragma unroll
        for (int ni = 0; ni < 4; ni++) {
            const int col = nblk * 128 + wn + ni * 8 + 2 * tig;
            float2 bb = *(const float2*)(bias + col);
            float2 v0, v1;
            v0.x = c[mi][ni][0] + bb.x; v0.y = c[mi][ni][1] + bb.y;
            v1.x = c[mi][ni][2] + bb.x; v1.y = c[mi][ni][3] + bb.y;
            *(float2*)(C + (size_t)row0 * N + col) = v0;
            *(float2*)(C + (size_t)(row0 + 8) * N + col) = v1;
        }
    }
}

// ---------------------------------------------------------------------------
// Flash attention fp16: 4 warps, TQ=64, TK=64, 4 CTAs/SM.
// Permuted tiles (stride 40): all B-frag loads are LDS.64.
// P register-resident; output written as permuted fp16 GEMM tiles.
// ---------------------------------------------------------------------------
__global__ void __launch_bounds__(128, 4)
flash_attn_h(const float* __restrict__ qkv, const uint32_t* __restrict__ kh,
             const uint32_t* __restrict__ vh, const float* __restrict__ mask,
             uint32_t* __restrict__ cxh)
{
    __shared__ uint32_t Qsw[64 * 40];
    __shared__ uint32_t Ksw[64 * 40];
    __shared__ uint32_t Vsw[64 * 40];
    __shared__ float    mk[64];

    const int bh = blockIdx.y;
    const int b  = bh >> 4;
    const int h  = bh & 15;
    const int q0 = blockIdx.x * 64;

    const int tid  = threadIdx.x;
    const int wid  = tid >> 5;
    const int lane = tid & 31;
    const int g    = lane >> 2;
    const int tig  = lane & 3;
    const int m0   = wid * 16;

    // Stage Q fp32 -> fp16 permuted smem
    const float* qptr = qkv + (size_t)b * S * (3 * NX) + (size_t)h * D;
    for (int idx = tid; idx < 64 * 16; idx += 128) {
        const int r  = idx >> 4;
        const int ve = idx & 15;
        float4 qa = *(const float4*)(qptr + (size_t)(q0 + r) * (3 * NX) + ve * 4);
        Qsw[r * 40 + permw(2 * ve)]     = pack2(qa.x, qa.y);
        Qsw[r * 40 + permw(2 * ve + 1)] = pack2(qa.z, qa.w);
    }
    __syncthreads();

    uint32_t aq[4][4];
#pragma unroll
    for (int s = 0; s < 4; s++) {
        const int base = s * 8 + 2 * tig;
        float2 lo = *(const float2*)&Qsw[(m0 + g) * 40 + base];
        float2 hi = *(const float2*)&Qsw[(m0 + g + 8) * 40 + base];
        aq[s][0] = __float_as_uint(lo.x);
        aq[s][1] = __float_as_uint(hi.x);
        aq[s][2] = __float_as_uint(lo.y);
        aq[s][3] = __float_as_uint(hi.y);
    }

    float mi0 = -CUDART_INF_F, mi1 = -CUDART_INF_F;
    float li0 = 0.f, li1 = 0.f;
    float o[8][4];
#pragma unroll
    for (int ni = 0; ni < 8; ni++)
#pragma unroll
        for (int j = 0; j < 4; j++) o[ni][j] = 0.f;

    for (int kt = 0; kt < 32; kt++) {
        __syncthreads();
        const uint4* ksrc = (const uint4*)(kh + ((size_t)bh * 32 + kt) * 2560);
        const uint4* vsrc = (const uint4*)(vh + ((size_t)bh * 32 + kt) * 2560);
        for (int i = tid; i < 1280; i += 128) {
            if (i < 640) ((uint4*)Ksw)[i] = ksrc[i];
            else         ((uint4*)Vsw)[i - 640] = vsrc[i - 640];
        }
        if (tid < 16)
            *(float4*)&mk[tid * 4] = *(const float4*)&mask[(size_t)b * S + kt * 64 + tid * 4];
        __syncthreads();

        // ---- QK^T (4 k16 steps over D=64)
        float c[8][4];
#pragma unroll
        for (int ni = 0; ni < 8; ni++)
#pragma unroll
            for (int j = 0; j < 4; j++) c[ni][j] = 0.f;

#pragma unroll
        for (int s = 0; s < 4; s++) {
            const int base = s * 8 + 2 * tig;
            uint32_t bf[8][2];
#pragma unroll
            for (int ni = 0; ni < 8; ni++) {
                float2 bb = *(const float2*)&Ksw[(ni * 8 + g) * 40 + base];
                bf[ni][0] = __float_as_uint(bb.x);
                bf[ni][1] = __float_as_uint(bb.y);
            }
#pragma unroll
            for (int ni = 0; ni < 8; ni++)
                mma16(c[ni], aq[s], bf[ni][0], bf[ni][1]);
        }

        // ---- scale + mask
#pragma unroll
        for (int ni = 0; ni < 8; ni++) {
            float2 mm = *(const float2*)&mk[ni * 8 + 2 * tig];
            c[ni][0] = fmaf(c[ni][0], 0.125f, mm.x);
            c[ni][1] = fmaf(c[ni][1], 0.125f, mm.y);
            c[ni][2] = fmaf(c[ni][2], 0.125f, mm.x);
            c[ni][3] = fmaf(c[ni][3], 0.125f, mm.y);
        }

        // ---- online softmax
        float mt0 = -CUDART_INF_F, mt1 = -CUDART_INF_F;
#pragma unroll
        for (int ni = 0; ni < 8; ni++) {
            mt0 = fmaxf(mt0, fmaxf(c[ni][0], c[ni][1]));
            mt1 = fmaxf(mt1, fmaxf(c[ni][2], c[ni][3]));
        }
        mt0 = fmaxf(mt0, __shfl_xor_sync(0xffffffffu, mt0, 1));
        mt0 = fmaxf(mt0, __shfl_xor_sync(0xffffffffu, mt0, 2));
        mt1 = fmaxf(mt1, __shfl_xor_sync(0xffffffffu, mt1, 1));
        mt1 = fmaxf(mt1, __shfl_xor_sync(0xffffffffu, mt1, 2));

        const float mn0 = fmaxf(mi0, mt0);
        const float mn1 = fmaxf(mi1, mt1);
        const float fac0 = __expf(mi0 - mn0);
        const float fac1 = __expf(mi1 - mn1);
        mi0 = mn0; mi1 = mn1;

        float lt0 = 0.f, lt1 = 0.f;
#pragma unroll
        for (int ni = 0; ni < 8; ni++) {
            c[ni][0] = __expf(c[ni][0] - mn0);
            c[ni][1] = __expf(c[ni][1] - mn0);
            c[ni][2] = __expf(c[ni][2] - mn1);
            c[ni][3] = __expf(c[ni][3] - mn1);
            lt0 += c[ni][0] + c[ni][1];
            lt1 += c[ni][2] + c[ni][3];
        }
        lt0 += __shfl_xor_sync(0xffffffffu, lt0, 1);
        lt0 += __shfl_xor_sync(0xffffffffu, lt0, 2);
        lt1 += __shfl_xor_sync(0xffffffffu, lt1, 1);
        lt1 += __shfl_xor_sync(0xffffffffu, lt1, 2);
        li0 = li0 * fac0 + lt0;
        li1 = li1 * fac1 + lt1;

#pragma unroll
        for (int ni = 0; ni < 8; ni++) {
            o[ni][0] *= fac0; o[ni][1] *= fac0;
            o[ni][2] *= fac1; o[ni][3] *= fac1;
        }

        // ---- O += P @ V : P packed directly from score regs
#pragma unroll
        for (int m = 0; m < 4; m++) {
            uint32_t af[4];
            af[0] = pack2(c[2 * m][0],     c[2 * m][1]);
            af[1] = pack2(c[2 * m][2],     c[2 * m][3]);
            af[2] = pack2(c[2 * m + 1][0], c[2 * m + 1][1]);
            af[3] = pack2(c[2 * m + 1][2], c[2 * m + 1][3]);
            const int base = m * 8 + 2 * tig;
            uint32_t bf[8][2];
#pragma unroll
            for (int ni = 0; ni < 8; ni++) {
                float2 bb = *(const float2*)&Vsw[(ni * 8 + g) * 40 + base];
                bf[ni][0] = __float_as_uint(bb.x);
                bf[ni][1] = __float_as_uint(bb.y);
            }
#pragma unroll
            for (int ni = 0; ni < 8; ni++)
                mma16(o[ni], af, bf[ni][0], bf[ni][1]);
        }
    }

    // ---- normalize + write ctx as permuted fp16 GEMM tiles
    const float inv0 = 1.f / li0;
    const float inv1 = 1.f / li1;
    const int row0 = (b << 11) + q0 + m0 + g;
#pragma unroll
    for (int ni = 0; ni < 8; ni++) {
        const int kblk = 2 * h + (ni >> 2);
        // logical word (ni&3)*4 + tig -> phys via permw (identical to old form)
        const int phys = ((ni & 2) << 2) | (tig << 1) | (ni & 1);
        {
            const int mblk = row0 >> 7, r = row0 & 127;
            cxh[(((size_t)mblk * 32 + kblk) * 128 + r) * 24 + phys] =
                pack2(o[ni][0] * inv0, o[ni][1] * inv0);
        }
        {
            const int row1 = row0 + 8;
            const int mblk = row1 >> 7, r = row1 & 127;
            cxh[(((size_t)mblk * 32 + kblk) * 128 + r) * 24 + phys] =
                pack2(o[ni][2] * inv1, o[ni][3] * inv1);
        }
    }
}

// ---------------------------------------------------------------------------
// Launch
// ---------------------------------------------------------------------------
extern "C" void kernel_launch(void* const* d_in, const int* in_sizes, int n_in,
                              void* d_out, int out_size)
{
    const float* x        = (const float*)d_in[0];
    const float* mask     = (const float*)d_in[1];
    const float* c_attn_w = (const float*)d_in[2];
    const float* c_attn_b = (const float*)d_in[3];
    const float* c_proj_w = (const float*)d_in[4];
    const float* c_proj_b = (const float*)d_in[5];
    float* out = (float*)d_out;

    float* qkv;
    uint32_t *xh, *w1h, *w2h, *cxh, *kh, *vh;
    cudaGetSymbolAddress((void**)&qkv, g_qkv);
    cudaGetSymbolAddress((void**)&xh,  g_xh);
    cudaGetSymbolAddress((void**)&w1h, g_w1h);
    cudaGetSymbolAddress((void**)&w2h, g_w2h);
    cudaGetSymbolAddress((void**)&cxh, g_cxh);
    cudaGetSymbolAddress((void**)&kh,  g_kh);
    cudaGetSymbolAddress((void**)&vh,  g_vh);

    // 0) Pre-convert to fp16 permuted tiles
    prep_x<<<dim3(32, 64), 256>>>(x, xh, NX, 32);
    transpose_h<<<dim3(3 * NX / 32, NX / 32), dim3(32, 8)>>>(c_attn_w, w1h, NX, 3 * NX, 32);
    transpose_h<<<dim3(NX / 32, NX / 32),     dim3(32, 8)>>>(c_proj_w, w2h, NX, NX, 32);

    const int gsm_bytes = 12288 * 4;   // 49152
    cudaFuncSetAttribute(gemm_h, cudaFuncAttributeMaxDynamicSharedMemorySize, gsm_bytes);

    // 1) QKV projection
    gemm_h<<<dim3(24, 64), 256, gsm_bytes>>>(xh, w1h, c_attn_b, qkv, 3 * NX, 32);

    // 1.5) Prep K/V
    prep_kv<<<dim3(32, 64), 256>>>(qkv, kh, vh);

    // 2) Flash attention -> ctx fp16 tiles
    flash_attn_h<<<dim3(32, 64), 128>>>(qkv, kh, vh, mask, cxh);

    // 3) Output projection
    gemm_h<<<dim3(8, 64), 256, gsm_bytes>>>(cxh, w2h, c_proj_b, out, NX, 32);
}

// round 16
// speedup vs baseline: 1.3752x; 1.3752x over previous
#include <cuda_runtime.h>
#include <cuda_fp16.h>
#include <math_constants.h>
#include <cstdint>

// Problem constants
#define B   4
#define S   2048
#define NX  1024
#define H   16
#define D   64
#define M_TOT (B * S)   // 8192

// ---------------------------------------------------------------------------
// Global scratch (uint32 units; halves live inside)
// GEMM tiles: [blk128][kblk32][128 rows][40 halves] (20 words/row)
// Flash tiles: [bh][kt][64 rows][72 halves] (36 words/row)
// ---------------------------------------------------------------------------
__device__ float    g_qkv[(size_t)M_TOT * 3 * NX];          // fp32 QKV
__device__ uint32_t g_xh [(size_t)64 * 32 * 128 * 20];      // x fp16 tiles
__device__ uint32_t g_w1h[(size_t)24 * 32 * 128 * 20];      // attn_w^T fp16 tiles
__device__ uint32_t g_w2h[(size_t)8  * 32 * 128 * 20];      // proj_w^T fp16 tiles
__device__ uint32_t g_cxh[(size_t)64 * 32 * 128 * 20];      // ctx fp16 tiles
__device__ uint32_t g_kh [(size_t)64 * 32 * 64 * 36];       // K fp16 tiles [key][d]
__device__ uint32_t g_vh [(size_t)64 * 32 * 64 * 36];       // V^T fp16 tiles [d][key]

// ---------------------------------------------------------------------------
// Helpers
// ---------------------------------------------------------------------------
__device__ __forceinline__ uint32_t pack2(float lo, float hi) {
    __half2 h = __floats2half2_rn(lo, hi);
    return *(uint32_t*)&h;
}

__device__ __forceinline__ uint32_t smem_u32(const void* p) {
    uint32_t a;
    asm("{ .reg .u64 t; cvta.to.shared.u64 t, %1; cvt.u32.u64 %0, t; }"
        : "=r"(a) : "l"(p));
    return a;
}

#define CP_ASYNC16(dst, src) \
    asm volatile("cp.async.cg.shared.global [%0], [%1], 16;" \
        :: "r"(dst), "l"(src) : "memory")
#define CP_COMMIT() asm volatile("cp.async.commit_group;" ::: "memory")
#define CP_WAIT0()  asm volatile("cp.async.wait_group 0;" ::: "memory")

// mma.sync m16n8k16 f16: D = A*B + D (fp32 accum)
__device__ __forceinline__ void mma16(float* c, const uint32_t* a,
                                      uint32_t b0, uint32_t b1) {
    asm volatile(
        "mma.sync.aligned.m16n8k16.row.col.f32.f16.f16.f32 "
        "{%0,%1,%2,%3}, {%4,%5,%6,%7}, {%8,%9}, {%0,%1,%2,%3};"
        : "+f"(c[0]), "+f"(c[1]), "+f"(c[2]), "+f"(c[3])
        : "r"(a[0]), "r"(a[1]), "r"(a[2]), "r"(a[3]), "r"(b0), "r"(b1));
}

// ---------------------------------------------------------------------------
// prep_x: x fp32 -> fp16 padded tiles. grid (K/32, M/128), 256 thr.
// ---------------------------------------------------------------------------
__global__ __launch_bounds__(256)
void prep_x(const float* __restrict__ x, uint32_t* __restrict__ xh,
            int K, int KB)
{
    const int kblk = blockIdx.x, mblk = blockIdx.y;
    const int tid = threadIdx.x;
    const size_t tile = ((size_t)mblk * KB + kblk) * 128 * 20;
    for (int idx = tid; idx < 128 * 8; idx += 256) {
        const int r = idx >> 3, ve = idx & 7;
        float4 v = *(const float4*)(x + (size_t)(mblk * 128 + r) * K + kblk * 32 + ve * 4);
        uint2 o;
        o.x = pack2(v.x, v.y);
        o.y = pack2(v.z, v.w);
        *(uint2*)&xh[tile + r * 20 + ve * 2] = o;
    }
}

// ---------------------------------------------------------------------------
// transpose_h: W[k][n] fp32 -> Wt fp16 tiles [nblk][kblk][128][40h].
// grid (N/32, K/32), block (32, 8).
// ---------------------------------------------------------------------------
__global__ void transpose_h(const float* __restrict__ W, uint32_t* __restrict__ Wt,
                            int K, int N, int KB)
{
    __shared__ float t[32][33];
    const int k0 = blockIdx.y * 32, n0 = blockIdx.x * 32;
    const int x = threadIdx.x, y = threadIdx.y;
#pragma unroll
    for (int i = 0; i < 32; i += 8)
        t[y + i][x] = W[(size_t)(k0 + y + i) * N + n0 + x];
    __syncthreads();
    __half* out = (__half*)Wt;
#pragma unroll
    for (int i = 0; i < 32; i += 8) {
        const int n = n0 + y + i, k = k0 + x;
        const size_t idx = (((size_t)(n >> 7) * KB + (k >> 5)) * 128 + (n & 127)) * 40 + (k & 31);
        out[idx] = __float2half_rn(t[x][y + i]);
    }
}

// ---------------------------------------------------------------------------
// prep_kv: qkv fp32 -> K tiles [key][d] fp16 and V^T tiles [d][key] fp16.
// grid (S/64, B*H), 256 thr.
// ---------------------------------------------------------------------------
__global__ __launch_bounds__(256)
void prep_kv(const float* __restrict__ qkv, uint32_t* __restrict__ kh,
             uint32_t* __restrict__ vh)
{
    __shared__ float vs[64][65];
    const int bh = blockIdx.y;
    const int b = bh >> 4, h = bh & 15;
    const int kt = blockIdx.x;
    const int s0 = kt * 64;
    const int tid = threadIdx.x;

    const float* kbase = qkv + (size_t)b * S * (3 * NX) + NX + h * D;
    const float* vbase = qkv + (size_t)b * S * (3 * NX) + 2 * NX + h * D;
    const size_t tile = ((size_t)bh * 32 + kt) * 64 * 36;

    for (int idx = tid; idx < 64 * 16; idx += 256) {
        const int r  = idx >> 4;
        const int ve = idx & 15;
        const size_t grow = (size_t)(s0 + r) * (3 * NX) + ve * 4;
        float4 kv = *(const float4*)(kbase + grow);
        uint2 ko;
        ko.x = pack2(kv.x, kv.y);
        ko.y = pack2(kv.z, kv.w);
        *(uint2*)&kh[tile + r * 36 + ve * 2] = ko;
        float4 vv = *(const float4*)(vbase + grow);
        vs[4 * ve + 0][r] = vv.x;
        vs[4 * ve + 1][r] = vv.y;
        vs[4 * ve + 2][r] = vv.z;
        vs[4 * ve + 3][r] = vv.w;
    }
    __syncthreads();

    for (int idx = tid; idx < 64 * 16; idx += 256) {
        const int d  = idx >> 4;
        const int ve = idx & 15;
        uint2 vo;
        vo.x = pack2(vs[d][4 * ve + 0], vs[d][4 * ve + 1]);
        vo.y = pack2(vs[d][4 * ve + 2], vs[d][4 * ve + 3]);
        *(uint2*)&vh[tile + d * 36 + ve * 2] = vo;
    }
}

// ---------------------------------------------------------------------------
// fp16 mma GEMM, 2-stage cp.async pipeline, ONE sync per K-tile-64:
// C[M,N] = A @ Bt^T + bias.  Block 128x128, 256 threads, warp tile 64x32.
// Stage = 2 k-blocks (K=64): A 5120 + B 5120 words = 40KB; 2 stages = 80KB.
// ---------------------------------------------------------------------------
__global__ __launch_bounds__(256)
void gemm_h(const uint32_t* __restrict__ At, const uint32_t* __restrict__ Bt,
            const float* __restrict__ bias, float* __restrict__ C,
            int N, int KB)
{
    extern __shared__ uint32_t gsw[];   // [2 stages][A 5120 | B 5120]

    const int tid  = threadIdx.x;
    const int wid  = tid >> 5;
    const int lane = tid & 31;
    const int g    = lane >> 2;
    const int tig  = lane & 3;

    const int nblk = blockIdx.x, mblk = blockIdx.y;
    const int wm = (wid >> 2) * 64;
    const int wn = (wid & 3) * 32;

    float c[4][4][4];
#pragma unroll
    for (int mi = 0; mi < 4; mi++)
#pragma unroll
        for (int ni = 0; ni < 4; ni++)
#pragma unroll
            for (int j = 0; j < 4; j++) c[mi][ni][j] = 0.f;

    const int KB2 = KB >> 1;
    const size_t abase = (size_t)mblk * KB * 2560;
    const size_t bbase = (size_t)nblk * KB * 2560;

    // issue stage kc2 into slot
    {
        const uint32_t au = smem_u32(gsw);
        const uint32_t bu = au + 5120 * 4;
        const uint4* asrc = (const uint4*)(At + abase);
        const uint4* bsrc = (const uint4*)(Bt + bbase);
        for (int i = tid; i < 1280; i += 256) {
            CP_ASYNC16(au + i * 16, asrc + i);
            CP_ASYNC16(bu + i * 16, bsrc + i);
        }
        CP_COMMIT();
    }

    for (int kc2 = 0; kc2 < KB2; kc2++) {
        CP_WAIT0();          // stage kc2 data arrived
        __syncthreads();     // all threads past previous stage's compute

        if (kc2 + 1 < KB2) { // prefetch next stage into the other slot
            const int slot = (kc2 + 1) & 1;
            const uint32_t au = smem_u32(gsw + slot * 10240);
            const uint32_t bu = au + 5120 * 4;
            const uint4* asrc = (const uint4*)(At + abase + (size_t)(kc2 + 1) * 5120);
            const uint4* bsrc = (const uint4*)(Bt + bbase + (size_t)(kc2 + 1) * 5120);
            for (int i = tid; i < 1280; i += 256) {
                CP_ASYNC16(au + i * 16, asrc + i);
                CP_ASYNC16(bu + i * 16, bsrc + i);
            }
            CP_COMMIT();
        }

        const uint32_t* Asl = gsw + (kc2 & 1) * 10240;
        const uint32_t* Bsl = Asl + 5120;

#pragma unroll
        for (int kb = 0; kb < 2; kb++) {
            const uint32_t* Ab = Asl + kb * 2560;
            const uint32_t* Bb = Bsl + kb * 2560;
#pragma unroll
            for (int s = 0; s < 2; s++) {
                const int kk = s * 8 + tig;
                uint32_t af[4][4], bf[4][2];
#pragma unroll
                for (int mi = 0; mi < 4; mi++) {
                    const int r = wm + mi * 16;
                    af[mi][0] = Ab[(r + g) * 20 + kk];
                    af[mi][1] = Ab[(r + g + 8) * 20 + kk];
                    af[mi][2] = Ab[(r + g) * 20 + kk + 4];
                    af[mi][3] = Ab[(r + g + 8) * 20 + kk + 4];
                }
#pragma unroll
                for (int ni = 0; ni < 4; ni++) {
                    const int r = wn + ni * 8;
                    bf[ni][0] = Bb[(r + g) * 20 + kk];
                    bf[ni][1] = Bb[(r + g) * 20 + kk + 4];
                }
#pragma unroll
                for (int mi = 0; mi < 4; mi++)
#pragma unroll
                    for (int ni = 0; ni < 4; ni++)
                        mma16(c[mi][ni], af[mi], bf[ni][0], bf[ni][1]);
            }
        }
    }

#pragma unroll
    for (int mi = 0; mi < 4; mi++) {
        const int row0 = mblk * 128 + wm + mi * 16 + g;
#pragma unroll
        for (int ni = 0; ni < 4; ni++) {
            const int col = nblk * 128 + wn + ni * 8 + 2 * tig;
            float2 bb = *(const float2*)(bias + col);
            float2 v0, v1;
            v0.x = c[mi][ni][0] + bb.x; v0.y = c[mi][ni][1] + bb.y;
            v1.x = c[mi][ni][2] + bb.x; v1.y = c[mi][ni][3] + bb.y;
            *(float2*)(C + (size_t)row0 * N + col) = v0;
            *(float2*)(C + (size_t)(row0 + 8) * N + col) = v1;
        }
    }
}

// ---------------------------------------------------------------------------
// Flash attention fp16 (round-13 proven): 4 warps, TQ=64, TK=64, 4 CTAs/SM.
// ---------------------------------------------------------------------------
__global__ void __launch_bounds__(128, 4)
flash_attn_h(const float* __restrict__ qkv, const uint32_t* __restrict__ kh,
             const uint32_t* __restrict__ vh, const float* __restrict__ mask,
             uint32_t* __restrict__ cxh)
{
    __shared__ uint32_t Qsw[64 * 36];
    __shared__ uint32_t Ksw[64 * 36];
    __shared__ uint32_t Vsw[64 * 36];
    __shared__ float    mk[64];

    const int bh = blockIdx.y;
    const int b  = bh >> 4;
    const int h  = bh & 15;
    const int q0 = blockIdx.x * 64;

    const int tid  = threadIdx.x;
    const int wid  = tid >> 5;
    const int lane = tid & 31;
    const int g    = lane >> 2;
    const int tig  = lane & 3;
    const int m0   = wid * 16;

    const float* qptr = qkv + (size_t)b * S * (3 * NX) + (size_t)h * D;
    for (int idx = tid; idx < 64 * 16; idx += 128) {
        const int r  = idx >> 4;
        const int ve = idx & 15;
        float4 qa = *(const float4*)(qptr + (size_t)(q0 + r) * (3 * NX) + ve * 4);
        uint2 o;
        o.x = pack2(qa.x, qa.y);
        o.y = pack2(qa.z, qa.w);
        *(uint2*)&Qsw[r * 36 + ve * 2] = o;
    }
    __syncthreads();

    uint32_t aq[4][4];
#pragma unroll
    for (int s = 0; s < 4; s++) {
        const int kk = s * 8 + tig;
        aq[s][0] = Qsw[(m0 + g) * 36 + kk];
        aq[s][1] = Qsw[(m0 + g + 8) * 36 + kk];
        aq[s][2] = Qsw[(m0 + g) * 36 + kk + 4];
        aq[s][3] = Qsw[(m0 + g + 8) * 36 + kk + 4];
    }

    float mi0 = -CUDART_INF_F, mi1 = -CUDART_INF_F;
    float li0 = 0.f, li1 = 0.f;
    float o[8][4];
#pragma unroll
    for (int ni = 0; ni < 8; ni++)
#pragma unroll
        for (int j = 0; j < 4; j++) o[ni][j] = 0.f;

    for (int kt = 0; kt < 32; kt++) {
        __syncthreads();
        const uint4* ksrc = (const uint4*)(kh + ((size_t)bh * 32 + kt) * 2304);
        const uint4* vsrc = (const uint4*)(vh + ((size_t)bh * 32 + kt) * 2304);
        for (int i = tid; i < 1152; i += 128) {
            if (i < 576) ((uint4*)Ksw)[i] = ksrc[i];
            else         ((uint4*)Vsw)[i - 576] = vsrc[i - 576];
        }
        if (tid < 16)
            *(float4*)&mk[tid * 4] = *(const float4*)&mask[(size_t)b * S + kt * 64 + tid * 4];
        __syncthreads();

        // ---- QK^T (4 k16 steps over D=64)
        float c[8][4];
#pragma unroll
        for (int ni = 0; ni < 8; ni++)
#pragma unroll
            for (int j = 0; j < 4; j++) c[ni][j] = 0.f;

#pragma unroll
        for (int s = 0; s < 4; s++) {
            const int kk = s * 8 + tig;
            uint32_t bf[8][2];
#pragma unroll
            for (int ni = 0; ni < 8; ni++) {
                bf[ni][0] = Ksw[(ni * 8 + g) * 36 + kk];
                bf[ni][1] = Ksw[(ni * 8 + g) * 36 + kk + 4];
            }
#pragma unroll
            for (int ni = 0; ni < 8; ni++)
                mma16(c[ni], aq[s], bf[ni][0], bf[ni][1]);
        }

        // ---- scale + mask
#pragma unroll
        for (int ni = 0; ni < 8; ni++) {
            float2 mm = *(const float2*)&mk[ni * 8 + 2 * tig];
            c[ni][0] = fmaf(c[ni][0], 0.125f, mm.x);
            c[ni][1] = fmaf(c[ni][1], 0.125f, mm.y);
            c[ni][2] = fmaf(c[ni][2], 0.125f, mm.x);
            c[ni][3] = fmaf(c[ni][3], 0.125f, mm.y);
        }

        // ---- online softmax
        float mt0 = -CUDART_INF_F, mt1 = -CUDART_INF_F;
#pragma unroll
        for (int ni = 0; ni < 8; ni++) {
            mt0 = fmaxf(mt0, fmaxf(c[ni][0], c[ni][1]));
            mt1 = fmaxf(mt1, fmaxf(c[ni][2], c[ni][3]));
        }
        mt0 = fmaxf(mt0, __shfl_xor_sync(0xffffffffu, mt0, 1));
        mt0 = fmaxf(mt0, __shfl_xor_sync(0xffffffffu, mt0, 2));
        mt1 = fmaxf(mt1, __shfl_xor_sync(0xffffffffu, mt1, 1));
        mt1 = fmaxf(mt1, __shfl_xor_sync(0xffffffffu, mt1, 2));

        const float mn0 = fmaxf(mi0, mt0);
        const float mn1 = fmaxf(mi1, mt1);
        const float fac0 = __expf(mi0 - mn0);
        const float fac1 = __expf(mi1 - mn1);
        mi0 = mn0; mi1 = mn1;

        float lt0 = 0.f, lt1 = 0.f;
#pragma unroll
        for (int ni = 0; ni < 8; ni++) {
            c[ni][0] = __expf(c[ni][0] - mn0);
            c[ni][1] = __expf(c[ni][1] - mn0);
            c[ni][2] = __expf(c[ni][2] - mn1);
            c[ni][3] = __expf(c[ni][3] - mn1);
            lt0 += c[ni][0] + c[ni][1];
            lt1 += c[ni][2] + c[ni][3];
        }
        lt0 += __shfl_xor_sync(0xffffffffu, lt0, 1);
        lt0 += __shfl_xor_sync(0xffffffffu, lt0, 2);
        lt1 += __shfl_xor_sync(0xffffffffu, lt1, 1);
        lt1 += __shfl_xor_sync(0xffffffffu, lt1, 2);
        li0 = li0 * fac0 + lt0;
        li1 = li1 * fac1 + lt1;

#pragma unroll
        for (int ni = 0; ni < 8; ni++) {
            o[ni][0] *= fac0; o[ni][1] *= fac0;
            o[ni][2] *= fac1; o[ni][3] *= fac1;
        }

        // ---- O += P @ V : P packed directly from score regs (4 k16 steps)
#pragma unroll
        for (int m = 0; m < 4; m++) {
            uint32_t af[4];
            af[0] = pack2(c[2 * m][0],     c[2 * m][1]);
            af[1] = pack2(c[2 * m][2],     c[2 * m][3]);
            af[2] = pack2(c[2 * m + 1][0], c[2 * m + 1][1]);
            af[3] = pack2(c[2 * m + 1][2], c[2 * m + 1][3]);
            const int kk = m * 8 + tig;
            uint32_t bf[8][2];
#pragma unroll
            for (int ni = 0; ni < 8; ni++) {
                bf[ni][0] = Vsw[(ni * 8 + g) * 36 + kk];
                bf[ni][1] = Vsw[(ni * 8 + g) * 36 + kk + 4];
            }
#pragma unroll
            for (int ni = 0; ni < 8; ni++)
                mma16(o[ni], af, bf[ni][0], bf[ni][1]);
        }
    }

    // ---- normalize + write ctx as fp16 tiles (proj GEMM A operand)
    const float inv0 = 1.f / li0;
    const float inv1 = 1.f / li1;
    const int row0 = (b << 11) + q0 + m0 + g;
#pragma unroll
    for (int ni = 0; ni < 8; ni++) {
        const int col = h * D + ni * 8 + 2 * tig;
        const int kblk = col >> 5, off = col & 31;
        {
            const int mblk = row0 >> 7, r = row0 & 127;
            cxh[(((size_t)mblk * 32 + kblk) * 128 + r) * 20 + (off >> 1)] =
                pack2(o[ni][0] * inv0, o[ni][1] * inv0);
        }
        {
            const int row1 = row0 + 8;
            const int mblk = row1 >> 7, r = row1 & 127;
            cxh[(((size_t)mblk * 32 + kblk) * 128 + r) * 20 + (off >> 1)] =
                pack2(o[ni][2] * inv1, o[ni][3] * inv1);
        }
    }
}

// ---------------------------------------------------------------------------
// Launch
// ---------------------------------------------------------------------------
extern "C" void kernel_launch(void* const* d_in, const int* in_sizes, int n_in,
                              void* d_out, int out_size)
{
    const float* x        = (const float*)d_in[0];
    const float* mask     = (const float*)d_in[1];
    const float* c_attn_w = (const float*)d_in[2];
    const float* c_attn_b = (const float*)d_in[3];
    const float* c_proj_w = (const float*)d_in[4];
    const float* c_proj_b = (const float*)d_in[5];
    float* out = (float*)d_out;

    float* qkv;
    uint32_t *xh, *w1h, *w2h, *cxh, *kh, *vh;
    cudaGetSymbolAddress((void**)&qkv, g_qkv);
    cudaGetSymbolAddress((void**)&xh,  g_xh);
    cudaGetSymbolAddress((void**)&w1h, g_w1h);
    cudaGetSymbolAddress((void**)&w2h, g_w2h);
    cudaGetSymbolAddress((void**)&cxh, g_cxh);
    cudaGetSymbolAddress((void**)&kh,  g_kh);
    cudaGetSymbolAddress((void**)&vh,  g_vh);

    // 0) Pre-convert to fp16 padded tiles
    prep_x<<<dim3(32, 64), 256>>>(x, xh, NX, 32);
    transpose_h<<<dim3(3 * NX / 32, NX / 32), dim3(32, 8)>>>(c_attn_w, w1h, NX, 3 * NX, 32);
    transpose_h<<<dim3(NX / 32, NX / 32),     dim3(32, 8)>>>(c_proj_w, w2h, NX, NX, 32);

    const int gsm_bytes = 2 * 10240 * 4;   // 81920
    cudaFuncSetAttribute(gemm_h, cudaFuncAttributeMaxDynamicSharedMemorySize, gsm_bytes);

    // 1) QKV projection (pipelined)
    gemm_h<<<dim3(24, 64), 256, gsm_bytes>>>(xh, w1h, c_attn_b, qkv, 3 * NX, 32);

    // 1.5) Prep K/V fp16 tiles
    prep_kv<<<dim3(32, 64), 256>>>(qkv, kh, vh);

    // 2) Flash attention -> ctx fp16 tiles
    flash_attn_h<<<dim3(32, 64), 128>>>(qkv, kh, vh, mask, cxh);

    // 3) Output projection (pipelined)
    gemm_h<<<dim3(8, 64), 256, gsm_bytes>>>(cxh, w2h, c_proj_b, out, NX, 32);
}

// round 17
// speedup vs baseline: 1.5581x; 1.1330x over previous
#include <cuda_runtime.h>
#include <cuda_fp16.h>
#include <math_constants.h>
#include <cstdint>

// Problem constants
#define B   4
#define S   2048
#define NX  1024
#define H   16
#define D   64
#define M_TOT (B * S)   // 8192

// ---------------------------------------------------------------------------
// Global scratch (uint32 units; halves live inside)
// GEMM tiles: [blk128][kblk32][128 rows][40 halves] (20 words/row)
// Flash tiles: [bh][kt][64 rows][72 halves] (36 words/row)
// ---------------------------------------------------------------------------
__device__ float    g_qkv[(size_t)M_TOT * 3 * NX];          // fp32 QKV
__device__ uint32_t g_xh [(size_t)64 * 32 * 128 * 20];      // x fp16 tiles
__device__ uint32_t g_w1h[(size_t)24 * 32 * 128 * 20];      // attn_w^T fp16 tiles
__device__ uint32_t g_w2h[(size_t)8  * 32 * 128 * 20];      // proj_w^T fp16 tiles
__device__ uint32_t g_cxh[(size_t)64 * 32 * 128 * 20];      // ctx fp16 tiles
__device__ uint32_t g_kh [(size_t)64 * 32 * 64 * 36];       // K fp16 tiles [key][d]
__device__ uint32_t g_vh [(size_t)64 * 32 * 64 * 36];       // V^T fp16 tiles [d][key]

// ---------------------------------------------------------------------------
// Helpers
// ---------------------------------------------------------------------------
__device__ __forceinline__ uint32_t pack2(float lo, float hi) {
    __half2 h = __floats2half2_rn(lo, hi);
    return *(uint32_t*)&h;
}

__device__ __forceinline__ uint32_t smem_u32(const void* p) {
    uint32_t a;
    asm("{ .reg .u64 t; cvta.to.shared.u64 t, %1; cvt.u32.u64 %0, t; }"
        : "=r"(a) : "l"(p));
    return a;
}

#define CP_ASYNC16(dst, src) \
    asm volatile("cp.async.cg.shared.global [%0], [%1], 16;" \
        :: "r"(dst), "l"(src) : "memory")
#define CP_COMMIT() asm volatile("cp.async.commit_group;" ::: "memory")
#define CP_WAIT0()  asm volatile("cp.async.wait_group 0;" ::: "memory")

// mma.sync m16n8k16 f16: D = A*B + D (fp32 accum)
__device__ __forceinline__ void mma16(float* c, const uint32_t* a,
                                      uint32_t b0, uint32_t b1) {
    asm volatile(
        "mma.sync.aligned.m16n8k16.row.col.f32.f16.f16.f32 "
        "{%0,%1,%2,%3}, {%4,%5,%6,%7}, {%8,%9}, {%0,%1,%2,%3};"
        : "+f"(c[0]), "+f"(c[1]), "+f"(c[2]), "+f"(c[3])
        : "r"(a[0]), "r"(a[1]), "r"(a[2]), "r"(a[3]), "r"(b0), "r"(b1));
}

// ---------------------------------------------------------------------------
// prep_x: x fp32 -> fp16 padded tiles. grid (K/32, M/128), 256 thr.
// ---------------------------------------------------------------------------
__global__ __launch_bounds__(256)
void prep_x(const float* __restrict__ x, uint32_t* __restrict__ xh,
            int K, int KB)
{
    const int kblk = blockIdx.x, mblk = blockIdx.y;
    const int tid = threadIdx.x;
    const size_t tile = ((size_t)mblk * KB + kblk) * 128 * 20;
    for (int idx = tid; idx < 128 * 8; idx += 256) {
        const int r = idx >> 3, ve = idx & 7;
        float4 v = *(const float4*)(x + (size_t)(mblk * 128 + r) * K + kblk * 32 + ve * 4);
        uint2 o;
        o.x = pack2(v.x, v.y);
        o.y = pack2(v.z, v.w);
        *(uint2*)&xh[tile + r * 20 + ve * 2] = o;
    }
}

// ---------------------------------------------------------------------------
// transpose_h: W[k][n] fp32 -> Wt fp16 tiles [nblk][kblk][128][40h].
// ---------------------------------------------------------------------------
__global__ void transpose_h(const float* __restrict__ W, uint32_t* __restrict__ Wt,
                            int K, int N, int KB)
{
    __shared__ float t[32][33];
    const int k0 = blockIdx.y * 32, n0 = blockIdx.x * 32;
    const int x = threadIdx.x, y = threadIdx.y;
#pragma unroll
    for (int i = 0; i < 32; i += 8)
        t[y + i][x] = W[(size_t)(k0 + y + i) * N + n0 + x];
    __syncthreads();
    __half* out = (__half*)Wt;
#pragma unroll
    for (int i = 0; i < 32; i += 8) {
        const int n = n0 + y + i, k = k0 + x;
        const size_t idx = (((size_t)(n >> 7) * KB + (k >> 5)) * 128 + (n & 127)) * 40 + (k & 31);
        out[idx] = __float2half_rn(t[x][y + i]);
    }
}

// ---------------------------------------------------------------------------
// prep_kv: qkv fp32 -> K tiles [key][d] fp16 and V^T tiles [d][key] fp16.
// ---------------------------------------------------------------------------
__global__ __launch_bounds__(256)
void prep_kv(const float* __restrict__ qkv, uint32_t* __restrict__ kh,
             uint32_t* __restrict__ vh)
{
    __shared__ float vs[64][65];
    const int bh = blockIdx.y;
    const int b = bh >> 4, h = bh & 15;
    const int kt = blockIdx.x;
    const int s0 = kt * 64;
    const int tid = threadIdx.x;

    const float* kbase = qkv + (size_t)b * S * (3 * NX) + NX + h * D;
    const float* vbase = qkv + (size_t)b * S * (3 * NX) + 2 * NX + h * D;
    const size_t tile = ((size_t)bh * 32 + kt) * 64 * 36;

    for (int idx = tid; idx < 64 * 16; idx += 256) {
        const int r  = idx >> 4;
        const int ve = idx & 15;
        const size_t grow = (size_t)(s0 + r) * (3 * NX) + ve * 4;
        float4 kv = *(const float4*)(kbase + grow);
        uint2 ko;
        ko.x = pack2(kv.x, kv.y);
        ko.y = pack2(kv.z, kv.w);
        *(uint2*)&kh[tile + r * 36 + ve * 2] = ko;
        float4 vv = *(const float4*)(vbase + grow);
        vs[4 * ve + 0][r] = vv.x;
        vs[4 * ve + 1][r] = vv.y;
        vs[4 * ve + 2][r] = vv.z;
        vs[4 * ve + 3][r] = vv.w;
    }
    __syncthreads();

    for (int idx = tid; idx < 64 * 16; idx += 256) {
        const int d  = idx >> 4;
        const int ve = idx & 15;
        uint2 vo;
        vo.x = pack2(vs[d][4 * ve + 0], vs[d][4 * ve + 1]);
        vo.y = pack2(vs[d][4 * ve + 2], vs[d][4 * ve + 3]);
        *(uint2*)&vh[tile + d * 36 + ve * 2] = vo;
    }
}

// ---------------------------------------------------------------------------
// fp16 mma GEMM, 2-stage cp.async pipeline (round-16 proven).
// ---------------------------------------------------------------------------
__global__ __launch_bounds__(256)
void gemm_h(const uint32_t* __restrict__ At, const uint32_t* __restrict__ Bt,
            const float* __restrict__ bias, float* __restrict__ C,
            int N, int KB)
{
    extern __shared__ uint32_t gsw[];   // [2 stages][A 5120 | B 5120]

    const int tid  = threadIdx.x;
    const int wid  = tid >> 5;
    const int lane = tid & 31;
    const int g    = lane >> 2;
    const int tig  = lane & 3;

    const int nblk = blockIdx.x, mblk = blockIdx.y;
    const int wm = (wid >> 2) * 64;
    const int wn = (wid & 3) * 32;

    float c[4][4][4];
#pragma unroll
    for (int mi = 0; mi < 4; mi++)
#pragma unroll
        for (int ni = 0; ni < 4; ni++)
#pragma unroll
            for (int j = 0; j < 4; j++) c[mi][ni][j] = 0.f;

    const int KB2 = KB >> 1;
    const size_t abase = (size_t)mblk * KB * 2560;
    const size_t bbase = (size_t)nblk * KB * 2560;

    {
        const uint32_t au = smem_u32(gsw);
        const uint32_t bu = au + 5120 * 4;
        const uint4* asrc = (const uint4*)(At + abase);
        const uint4* bsrc = (const uint4*)(Bt + bbase);
        for (int i = tid; i < 1280; i += 256) {
            CP_ASYNC16(au + i * 16, asrc + i);
            CP_ASYNC16(bu + i * 16, bsrc + i);
        }
        CP_COMMIT();
    }

    for (int kc2 = 0; kc2 < KB2; kc2++) {
        CP_WAIT0();
        __syncthreads();

        if (kc2 + 1 < KB2) {
            const int slot = (kc2 + 1) & 1;
            const uint32_t au = smem_u32(gsw + slot * 10240);
            const uint32_t bu = au + 5120 * 4;
            const uint4* asrc = (const uint4*)(At + abase + (size_t)(kc2 + 1) * 5120);
            const uint4* bsrc = (const uint4*)(Bt + bbase + (size_t)(kc2 + 1) * 5120);
            for (int i = tid; i < 1280; i += 256) {
                CP_ASYNC16(au + i * 16, asrc + i);
                CP_ASYNC16(bu + i * 16, bsrc + i);
            }
            CP_COMMIT();
        }

        const uint32_t* Asl = gsw + (kc2 & 1) * 10240;
        const uint32_t* Bsl = Asl + 5120;

#pragma unroll
        for (int kb = 0; kb < 2; kb++) {
            const uint32_t* Ab = Asl + kb * 2560;
            const uint32_t* Bb = Bsl + kb * 2560;
#pragma unroll
            for (int s = 0; s < 2; s++) {
                const int kk = s * 8 + tig;
                uint32_t af[4][4], bf[4][2];
#pragma unroll
                for (int mi = 0; mi < 4; mi++) {
                    const int r = wm + mi * 16;
                    af[mi][0] = Ab[(r + g) * 20 + kk];
                    af[mi][1] = Ab[(r + g + 8) * 20 + kk];
                    af[mi][2] = Ab[(r + g) * 20 + kk + 4];
                    af[mi][3] = Ab[(r + g + 8) * 20 + kk + 4];
                }
#pragma unroll
                for (int ni = 0; ni < 4; ni++) {
                    const int r = wn + ni * 8;
                    bf[ni][0] = Bb[(r + g) * 20 + kk];
                    bf[ni][1] = Bb[(r + g) * 20 + kk + 4];
                }
#pragma unroll
                for (int mi = 0; mi < 4; mi++)
#pragma unroll
                    for (int ni = 0; ni < 4; ni++)
                        mma16(c[mi][ni], af[mi], bf[ni][0], bf[ni][1]);
            }
        }
    }

#pragma unroll
    for (int mi = 0; mi < 4; mi++) {
        const int row0 = mblk * 128 + wm + mi * 16 + g;
#pragma unroll
        for (int ni = 0; ni < 4; ni++) {
            const int col = nblk * 128 + wn + ni * 8 + 2 * tig;
            float2 bb = *(const float2*)(bias + col);
            float2 v0, v1;
            v0.x = c[mi][ni][0] + bb.x; v0.y = c[mi][ni][1] + bb.y;
            v1.x = c[mi][ni][2] + bb.x; v1.y = c[mi][ni][3] + bb.y;
            *(float2*)(C + (size_t)row0 * N + col) = v0;
            *(float2*)(C + (size_t)(row0 + 8) * N + col) = v1;
        }
    }
}

// ---------------------------------------------------------------------------
// Flash attention fp16, 2-stage cp.async K/V pipeline, 1 sync per tile.
// 4 warps, TQ=64, TK=64, 4 CTAs/SM.
// smem: Q 9KB + 2 stages x (K 9KB/2 + V 9KB/2 + mask 256B) ~= 46.6 KB.
// ---------------------------------------------------------------------------
__global__ void __launch_bounds__(128, 4)
flash_attn_h(const float* __restrict__ qkv, const uint32_t* __restrict__ kh,
             const uint32_t* __restrict__ vh, const float* __restrict__ mask,
             uint32_t* __restrict__ cxh)
{
    __shared__ uint32_t Qsw[64 * 36];
    __shared__ uint32_t Ksw[2][64 * 36];
    __shared__ uint32_t Vsw[2][64 * 36];
    __shared__ float    mk[2][64];

    const int bh = blockIdx.y;
    const int b  = bh >> 4;
    const int h  = bh & 15;
    const int q0 = blockIdx.x * 64;

    const int tid  = threadIdx.x;
    const int wid  = tid >> 5;
    const int lane = tid & 31;
    const int g    = lane >> 2;
    const int tig  = lane & 3;
    const int m0   = wid * 16;

    // Stage Q fp32 -> fp16 smem
    const float* qptr = qkv + (size_t)b * S * (3 * NX) + (size_t)h * D;
    for (int idx = tid; idx < 64 * 16; idx += 128) {
        const int r  = idx >> 4;
        const int ve = idx & 15;
        float4 qa = *(const float4*)(qptr + (size_t)(q0 + r) * (3 * NX) + ve * 4);
        uint2 o;
        o.x = pack2(qa.x, qa.y);
        o.y = pack2(qa.z, qa.w);
        *(uint2*)&Qsw[r * 36 + ve * 2] = o;
    }

    const uint32_t* khb = kh + (size_t)bh * 32 * 2304;
    const uint32_t* vhb = vh + (size_t)bh * 32 * 2304;
    const float*    mkb = mask + (size_t)b * S;

    // Prologue: issue stage 0
    {
        const uint32_t ku = smem_u32(Ksw[0]);
        const uint32_t vu = smem_u32(Vsw[0]);
        const uint4* ksrc = (const uint4*)(khb);
        const uint4* vsrc = (const uint4*)(vhb);
        for (int i = tid; i < 576; i += 128) {
            CP_ASYNC16(ku + i * 16, ksrc + i);
            CP_ASYNC16(vu + i * 16, vsrc + i);
        }
        if (tid < 16) CP_ASYNC16(smem_u32(mk[0]) + tid * 16, mkb + tid * 4);
        CP_COMMIT();
    }
    __syncthreads();   // Q staged before fragment hoist

    uint32_t aq[4][4];
#pragma unroll
    for (int s = 0; s < 4; s++) {
        const int kk = s * 8 + tig;
        aq[s][0] = Qsw[(m0 + g) * 36 + kk];
        aq[s][1] = Qsw[(m0 + g + 8) * 36 + kk];
        aq[s][2] = Qsw[(m0 + g) * 36 + kk + 4];
        aq[s][3] = Qsw[(m0 + g + 8) * 36 + kk + 4];
    }

    float mi0 = -CUDART_INF_F, mi1 = -CUDART_INF_F;
    float li0 = 0.f, li1 = 0.f;
    float o[8][4];
#pragma unroll
    for (int ni = 0; ni < 8; ni++)
#pragma unroll
        for (int j = 0; j < 4; j++) o[ni][j] = 0.f;

    for (int kt = 0; kt < 32; kt++) {
        CP_WAIT0();          // stage kt arrived
        __syncthreads();     // everyone done computing on the slot being refilled

        if (kt + 1 < 32) {   // issue stage kt+1 into other slot
            const int slot = (kt + 1) & 1;
            const uint32_t ku = smem_u32(Ksw[slot]);
            const uint32_t vu = smem_u32(Vsw[slot]);
            const uint4* ksrc = (const uint4*)(khb + (size_t)(kt + 1) * 2304);
            const uint4* vsrc = (const uint4*)(vhb + (size_t)(kt + 1) * 2304);
            for (int i = tid; i < 576; i += 128) {
                CP_ASYNC16(ku + i * 16, ksrc + i);
                CP_ASYNC16(vu + i * 16, vsrc + i);
            }
            if (tid < 16)
                CP_ASYNC16(smem_u32(mk[slot]) + tid * 16, mkb + (kt + 1) * 64 + tid * 4);
            CP_COMMIT();
        }

        const uint32_t* Kc = Ksw[kt & 1];
        const uint32_t* Vc = Vsw[kt & 1];
        const float*    mc = mk[kt & 1];

        // ---- QK^T (4 k16 steps over D=64)
        float c[8][4];
#pragma unroll
        for (int ni = 0; ni < 8; ni++)
#pragma unroll
            for (int j = 0; j < 4; j++) c[ni][j] = 0.f;

#pragma unroll
        for (int s = 0; s < 4; s++) {
            const int kk = s * 8 + tig;
            uint32_t bf[8][2];
#pragma unroll
            for (int ni = 0; ni < 8; ni++) {
                bf[ni][0] = Kc[(ni * 8 + g) * 36 + kk];
                bf[ni][1] = Kc[(ni * 8 + g) * 36 + kk + 4];
            }
#pragma unroll
            for (int ni = 0; ni < 8; ni++)
                mma16(c[ni], aq[s], bf[ni][0], bf[ni][1]);
        }

        // ---- scale + mask
#pragma unroll
        for (int ni = 0; ni < 8; ni++) {
            float2 mm = *(const float2*)&mc[ni * 8 + 2 * tig];
            c[ni][0] = fmaf(c[ni][0], 0.125f, mm.x);
            c[ni][1] = fmaf(c[ni][1], 0.125f, mm.y);
            c[ni][2] = fmaf(c[ni][2], 0.125f, mm.x);
            c[ni][3] = fmaf(c[ni][3], 0.125f, mm.y);
        }

        // ---- online softmax
        float mt0 = -CUDART_INF_F, mt1 = -CUDART_INF_F;
#pragma unroll
        for (int ni = 0; ni < 8; ni++) {
            mt0 = fmaxf(mt0, fmaxf(c[ni][0], c[ni][1]));
            mt1 = fmaxf(mt1, fmaxf(c[ni][2], c[ni][3]));
        }
        mt0 = fmaxf(mt0, __shfl_xor_sync(0xffffffffu, mt0, 1));
        mt0 = fmaxf(mt0, __shfl_xor_sync(0xffffffffu, mt0, 2));
        mt1 = fmaxf(mt1, __shfl_xor_sync(0xffffffffu, mt1, 1));
        mt1 = fmaxf(mt1, __shfl_xor_sync(0xffffffffu, mt1, 2));

        const float mn0 = fmaxf(mi0, mt0);
        const float mn1 = fmaxf(mi1, mt1);
        const float fac0 = __expf(mi0 - mn0);
        const float fac1 = __expf(mi1 - mn1);
        mi0 = mn0; mi1 = mn1;

        float lt0 = 0.f, lt1 = 0.f;
#pragma unroll
        for (int ni = 0; ni < 8; ni++) {
            c[ni][0] = __expf(c[ni][0] - mn0);
            c[ni][1] = __expf(c[ni][1] - mn0);
            c[ni][2] = __expf(c[ni][2] - mn1);
            c[ni][3] = __expf(c[ni][3] - mn1);
            lt0 += c[ni][0] + c[ni][1];
            lt1 += c[ni][2] + c[ni][3];
        }
        lt0 += __shfl_xor_sync(0xffffffffu, lt0, 1);
        lt0 += __shfl_xor_sync(0xffffffffu, lt0, 2);
        lt1 += __shfl_xor_sync(0xffffffffu, lt1, 1);
        lt1 += __shfl_xor_sync(0xffffffffu, lt1, 2);
        li0 = li0 * fac0 + lt0;
        li1 = li1 * fac1 + lt1;

#pragma unroll
        for (int ni = 0; ni < 8; ni++) {
            o[ni][0] *= fac0; o[ni][1] *= fac0;
            o[ni][2] *= fac1; o[ni][3] *= fac1;
        }

        // ---- O += P @ V : P packed from score regs
#pragma unroll
        for (int m = 0; m < 4; m++) {
            uint32_t af[4];
            af[0] = pack2(c[2 * m][0],     c[2 * m][1]);
            af[1] = pack2(c[2 * m][2],     c[2 * m][3]);
            af[2] = pack2(c[2 * m + 1][0], c[2 * m + 1][1]);
            af[3] = pack2(c[2 * m + 1][2], c[2 * m + 1][3]);
            const int kk = m * 8 + tig;
            uint32_t bf[8][2];
#pragma unroll
            for (int ni = 0; ni < 8; ni++) {
                bf[ni][0] = Vc[(ni * 8 + g) * 36 + kk];
                bf[ni][1] = Vc[(ni * 8 + g) * 36 + kk + 4];
            }
#pragma unroll
            for (int ni = 0; ni < 8; ni++)
                mma16(o[ni], af, bf[ni][0], bf[ni][1]);
        }
    }

    // ---- normalize + write ctx as fp16 tiles (proj GEMM A operand)
    const float inv0 = 1.f / li0;
    const float inv1 = 1.f / li1;
    const int row0 = (b << 11) + q0 + m0 + g;
#pragma unroll
    for (int ni = 0; ni < 8; ni++) {
        const int col = h * D + ni * 8 + 2 * tig;
        const int kblk = col >> 5, off = col & 31;
        {
            const int mblk = row0 >> 7, r = row0 & 127;
            cxh[(((size_t)mblk * 32 + kblk) * 128 + r) * 20 + (off >> 1)] =
                pack2(o[ni][0] * inv0, o[ni][1] * inv0);
        }
        {
            const int row1 = row0 + 8;
            const int mblk = row1 >> 7, r = row1 & 127;
            cxh[(((size_t)mblk * 32 + kblk) * 128 + r) * 20 + (off >> 1)] =
                pack2(o[ni][2] * inv1, o[ni][3] * inv1);
        }
    }
}

// ---------------------------------------------------------------------------
// Launch
// ---------------------------------------------------------------------------
extern "C" void kernel_launch(void* const* d_in, const int* in_sizes, int n_in,
                              void* d_out, int out_size)
{
    const float* x        = (const float*)d_in[0];
    const float* mask     = (const float*)d_in[1];
    const float* c_attn_w = (const float*)d_in[2];
    const float* c_attn_b = (const float*)d_in[3];
    const float* c_proj_w = (const float*)d_in[4];
    const float* c_proj_b = (const float*)d_in[5];
    float* out = (float*)d_out;

    float* qkv;
    uint32_t *xh, *w1h, *w2h, *cxh, *kh, *vh;
    cudaGetSymbolAddress((void**)&qkv, g_qkv);
    cudaGetSymbolAddress((void**)&xh,  g_xh);
    cudaGetSymbolAddress((void**)&w1h, g_w1h);
    cudaGetSymbolAddress((void**)&w2h, g_w2h);
    cudaGetSymbolAddress((void**)&cxh, g_cxh);
    cudaGetSymbolAddress((void**)&kh,  g_kh);
    cudaGetSymbolAddress((void**)&vh,  g_vh);

    // 0) Pre-convert to fp16 padded tiles
    prep_x<<<dim3(32, 64), 256>>>(x, xh, NX, 32);
    transpose_h<<<dim3(3 * NX / 32, NX / 32), dim3(32, 8)>>>(c_attn_w, w1h, NX, 3 * NX, 32);
    transpose_h<<<dim3(NX / 32, NX / 32),     dim3(32, 8)>>>(c_proj_w, w2h, NX, NX, 32);

    const int gsm_bytes = 2 * 10240 * 4;   // 81920
    cudaFuncSetAttribute(gemm_h, cudaFuncAttributeMaxDynamicSharedMemorySize, gsm_bytes);

    // 1) QKV projection (pipelined)
    gemm_h<<<dim3(24, 64), 256, gsm_bytes>>>(xh, w1h, c_attn_b, qkv, 3 * NX, 32);

    // 1.5) Prep K/V fp16 tiles
    prep_kv<<<dim3(32, 64), 256>>>(qkv, kh, vh);

    // 2) Flash attention (pipelined) -> ctx fp16 tiles
    flash_attn_h<<<dim3(32, 64), 128>>>(qkv, kh, vh, mask, cxh);

    // 3) Output projection (pipelined)
    gemm_h<<<dim3(8, 64), 256, gsm_bytes>>>(cxh, w2h, c_proj_b, out, NX, 32);
}